// round 2
// baseline (speedup 1.0000x reference)
#include <cuda_runtime.h>

#define B_   16
#define T_   200
#define U1_  101
#define U_   100
#define V_   512
#define NEGV (-1e30f)

// Scratch: per-cell blank/emit log-probs, per-batch costs, completion counter.
__device__ float g_blank[B_ * T_ * U1_];
__device__ float g_emit [B_ * T_ * U1_];
__device__ volatile float g_cost [B_];
__device__ int   g_done = 0;

// ---------------------------------------------------------------------------
// Kernel 1: per-row log-softmax stats. One warp per (b,t,u) row of V=512.
// Each lane holds 16 floats (4 x float4), single pass over HBM.
// ---------------------------------------------------------------------------
__global__ void __launch_bounds__(256) rnnt_softmax_kernel(
    const float* __restrict__ acts,
    const int*   __restrict__ labels,
    const int*   __restrict__ label_lens)
{
    const int warp = (blockIdx.x * blockDim.x + threadIdx.x) >> 5;
    const int lane = threadIdx.x & 31;
    const int R = B_ * T_ * U1_;
    if (warp >= R) return;

    const int u = warp % U1_;
    const int b = warp / (T_ * U1_);

    const float4* __restrict__ p =
        reinterpret_cast<const float4*>(acts + (size_t)warp * V_);
    float4 v0 = p[lane];
    float4 v1 = p[lane + 32];
    float4 v2 = p[lane + 64];
    float4 v3 = p[lane + 96];

    // max reduce
    float m = fmaxf(fmaxf(fmaxf(v0.x, v0.y), fmaxf(v0.z, v0.w)),
                    fmaxf(fmaxf(v1.x, v1.y), fmaxf(v1.z, v1.w)));
    m = fmaxf(m, fmaxf(fmaxf(fmaxf(v2.x, v2.y), fmaxf(v2.z, v2.w)),
                       fmaxf(fmaxf(v3.x, v3.y), fmaxf(v3.z, v3.w))));
    #pragma unroll
    for (int off = 16; off > 0; off >>= 1)
        m = fmaxf(m, __shfl_xor_sync(0xffffffffu, m, off));

    // sum(exp(x - m)) reduce
    float s = __expf(v0.x - m) + __expf(v0.y - m) + __expf(v0.z - m) + __expf(v0.w - m)
            + __expf(v1.x - m) + __expf(v1.y - m) + __expf(v1.z - m) + __expf(v1.w - m)
            + __expf(v2.x - m) + __expf(v2.y - m) + __expf(v2.z - m) + __expf(v2.w - m)
            + __expf(v3.x - m) + __expf(v3.y - m) + __expf(v3.z - m) + __expf(v3.w - m);
    #pragma unroll
    for (int off = 16; off > 0; off >>= 1)
        s += __shfl_xor_sync(0xffffffffu, s, off);

    const float lse = m + __logf(s);

    // blank logit = element 0 (lane 0, v0.x)
    const float blank_logit = __shfl_sync(0xffffffffu, v0.x, 0);

    // label logit: uniform label index across the warp
    int lbl = 0;
    if (u < U_) lbl = labels[b * U_ + u];
    const int j   = lbl >> 2;
    const int src = j & 31;
    const int k   = j >> 5;
    const int c   = lbl & 3;
    float4 sel = (k == 0) ? v0 : (k == 1) ? v1 : (k == 2) ? v2 : v3;
    float cand = (c == 0) ? sel.x : (c == 1) ? sel.y : (c == 2) ? sel.z : sel.w;
    const float label_logit = __shfl_sync(0xffffffffu, cand, src);

    if (lane == 0) {
        const int llen = label_lens[b];
        g_blank[warp] = blank_logit - lse;
        g_emit [warp] = (u < llen) ? (label_logit - lse) : NEGV;
    }
}

// ---------------------------------------------------------------------------
// Kernel 2: forward DP per batch — warp-synchronous anti-diagonal wavefront.
// alpha state lives in registers: lane L holds u = 4L .. 4L+3.
// Cell (d,u) needs prev-diagonal values at u (own reg) and u-1 (own reg or
// one shfl_up per diagonal). No block barriers in the main loop.
// Warps 1..3 only help stage blank/emit into SMEM, then exit.
// Finalize (mean over batches) is folded in via threadfence-reduction.
// ---------------------------------------------------------------------------
__global__ void __launch_bounds__(128) rnnt_dp_kernel(
    const int* __restrict__ act_lens,
    const int* __restrict__ label_lens,
    float* __restrict__ out)
{
    extern __shared__ float sm[];
    float* blank_s = sm;               // T_*U1_ = 20200
    float* emit_s  = sm + T_ * U1_;

    const int b   = blockIdx.x;
    const int tid = threadIdx.x;

    // Stage this batch's blank/emit into SMEM (coalesced float4, 128 threads).
    {
        const float4* gb = reinterpret_cast<const float4*>(g_blank + b * T_ * U1_);
        const float4* ge = reinterpret_cast<const float4*>(g_emit  + b * T_ * U1_);
        float4* sb = reinterpret_cast<float4*>(blank_s);
        float4* se = reinterpret_cast<float4*>(emit_s);
        const int N4 = (T_ * U1_) / 4;   // 5050
        #pragma unroll 4
        for (int i = tid; i < N4; i += 128) {
            sb[i] = gb[i];
            se[i] = ge[i];
        }
    }
    __syncthreads();
    if (tid >= 32) return;            // warp 0 runs the DP alone

    const int lane  = tid;
    const int alen  = act_lens[b];
    const int llen  = label_lens[b];
    const int dstar = (alen - 1) + llen;
    const int ubase = lane << 2;

    // d = 0 diagonal: only (0,0) = 0.
    float a0 = (lane == 0) ? 0.0f : NEGV;
    float a1 = NEGV, a2 = NEGV, a3 = NEGV;
    float res = NEGV;

    for (int d = 1; d <= dstar; ++d) {
        const float am1 = __shfl_up_sync(0xffffffffu, a3, 1); // alpha[u-1] for u=ubase
        float ac[4] = { a0, a1, a2, a3 };     // prev diag at u
        float ap[4] = { am1, a0, a1, a2 };    // prev diag at u-1
        float na[4];
        #pragma unroll
        for (int j = 0; j < 4; ++j) {
            const int u = ubase + j;
            const int t = d - u;
            float v = NEGV;
            if (u < U1_ && t >= 0 && t < T_) {
                const float top  = (t >= 1)
                    ? ac[j] + blank_s[(t - 1) * U1_ + u] : NEGV;
                const float left = (u >= 1)
                    ? ap[j] + emit_s[t * U1_ + u - 1]    : NEGV;
                const float mx = fmaxf(top, left);
                const float mn = fminf(top, left);
                v = mx + __logf(1.0f + __expf(mn - mx));
            }
            na[j] = v;
            if (d == dstar && u == llen) res = v;
        }
        a0 = na[0]; a1 = na[1]; a2 = na[2]; a3 = na[3];
    }

    // Lane owning u == llen writes this batch's cost.
    if (llen >= ubase && llen < ubase + 4)
        g_cost[b] = -(res + blank_s[(alen - 1) * U1_ + llen]);
    __syncwarp();
    __threadfence();

    // Last block to finish performs the deterministic fixed-order mean.
    if (lane == 0) {
        const int prev = atomicAdd(&g_done, 1);
        if (prev == B_ - 1) {
            __threadfence();
            float s = 0.0f;
            #pragma unroll
            for (int i = 0; i < B_; ++i) s += g_cost[i];
            out[0] = s / (float)B_;
            g_done = 0;               // reset for next graph replay
        }
    }
}

// ---------------------------------------------------------------------------
extern "C" void kernel_launch(void* const* d_in, const int* in_sizes, int n_in,
                              void* d_out, int out_size)
{
    const float* acts       = (const float*)d_in[0];
    const int*   labels     = (const int*)  d_in[1];
    const int*   act_lens   = (const int*)  d_in[2];
    const int*   label_lens = (const int*)  d_in[3];
    float*       out        = (float*)      d_out;

    const int rows   = B_ * T_ * U1_;          // 323,200 rows
    const int wpb    = 8;                      // warps per block
    const int blocks = (rows + wpb - 1) / wpb; // 40,400

    rnnt_softmax_kernel<<<blocks, wpb * 32>>>(acts, labels, label_lens);

    const size_t smemBytes = (size_t)2 * T_ * U1_ * sizeof(float);  // 161,600 B
    cudaFuncSetAttribute(rnnt_dp_kernel,
                         cudaFuncAttributeMaxDynamicSharedMemorySize,
                         (int)smemBytes);
    rnnt_dp_kernel<<<B_, 128, smemBytes>>>(act_lens, label_lens, out);
}

// round 3
// speedup vs baseline: 1.5742x; 1.5742x over previous
#include <cuda_runtime.h>

#define B_   16
#define T_   200
#define U1_  101
#define U_   100
#define V_   512
#define S_   102          /* padded SMEM row stride; S_-1 odd => conflict-free LDS */
#define NEGV (-1e30f)

// Scratch: per-cell blank/emit log-probs, per-batch costs, completion counter.
__device__ float g_blank[B_ * T_ * U1_];
__device__ float g_emit [B_ * T_ * U1_];
__device__ volatile float g_cost[B_];
__device__ int   g_done = 0;

// ---------------------------------------------------------------------------
// Kernel 1: per-row log-softmax stats. One warp per (b,t,u) row of V=512.
// Each lane holds 16 floats (4 x float4), single pass over HBM, streaming.
// ---------------------------------------------------------------------------
__global__ void __launch_bounds__(256) rnnt_softmax_kernel(
    const float* __restrict__ acts,
    const int*   __restrict__ labels,
    const int*   __restrict__ label_lens)
{
    const int warp = (blockIdx.x * blockDim.x + threadIdx.x) >> 5;
    const int lane = threadIdx.x & 31;
    const int R = B_ * T_ * U1_;
    if (warp >= R) return;

    const int u = warp % U1_;
    const int b = warp / (T_ * U1_);

    const float4* __restrict__ p =
        reinterpret_cast<const float4*>(acts + (size_t)warp * V_);
    float4 v0 = __ldcs(p + lane);
    float4 v1 = __ldcs(p + lane + 32);
    float4 v2 = __ldcs(p + lane + 64);
    float4 v3 = __ldcs(p + lane + 96);

    // max reduce
    float m = fmaxf(fmaxf(fmaxf(v0.x, v0.y), fmaxf(v0.z, v0.w)),
                    fmaxf(fmaxf(v1.x, v1.y), fmaxf(v1.z, v1.w)));
    m = fmaxf(m, fmaxf(fmaxf(fmaxf(v2.x, v2.y), fmaxf(v2.z, v2.w)),
                       fmaxf(fmaxf(v3.x, v3.y), fmaxf(v3.z, v3.w))));
    #pragma unroll
    for (int off = 16; off > 0; off >>= 1)
        m = fmaxf(m, __shfl_xor_sync(0xffffffffu, m, off));

    // sum(exp(x - m)) reduce
    float s = __expf(v0.x - m) + __expf(v0.y - m) + __expf(v0.z - m) + __expf(v0.w - m)
            + __expf(v1.x - m) + __expf(v1.y - m) + __expf(v1.z - m) + __expf(v1.w - m)
            + __expf(v2.x - m) + __expf(v2.y - m) + __expf(v2.z - m) + __expf(v2.w - m)
            + __expf(v3.x - m) + __expf(v3.y - m) + __expf(v3.z - m) + __expf(v3.w - m);
    #pragma unroll
    for (int off = 16; off > 0; off >>= 1)
        s += __shfl_xor_sync(0xffffffffu, s, off);

    const float lse = m + __logf(s);

    // blank logit = element 0 (lane 0, v0.x)
    const float blank_logit = __shfl_sync(0xffffffffu, v0.x, 0);

    // label logit: uniform label index across the warp
    int lbl = 0;
    if (u < U_) lbl = labels[b * U_ + u];
    const int j   = lbl >> 2;
    const int src = j & 31;
    const int k   = j >> 5;
    const int c   = lbl & 3;
    float4 sel = (k == 0) ? v0 : (k == 1) ? v1 : (k == 2) ? v2 : v3;
    float cand = (c == 0) ? sel.x : (c == 1) ? sel.y : (c == 2) ? sel.z : sel.w;
    const float label_logit = __shfl_sync(0xffffffffu, cand, src);

    if (lane == 0) {
        const int llen = label_lens[b];
        g_blank[warp] = blank_logit - lse;
        g_emit [warp] = (u < llen) ? (label_logit - lse) : NEGV;
    }
}

// ---------------------------------------------------------------------------
// Kernel 2: forward DP per batch — warp-synchronous anti-diagonal wavefront.
// Lane L holds alpha for u = 4L..4L+3 in registers. One shfl_up per diagonal.
// SMEM row stride 102 (odd u-stride 101) => conflict-free LDS.
// Branch-free inner loop: running offsets, clamped loads, FSEL validity.
// Finalize (mean over batches) folded in via threadfence-reduction.
// ---------------------------------------------------------------------------
__global__ void __launch_bounds__(128) rnnt_dp_kernel(
    const int* __restrict__ act_lens,
    const int* __restrict__ label_lens,
    float* __restrict__ out)
{
    extern __shared__ float sm[];
    float* blank_s = sm;               // T_*S_ = 20400
    float* emit_s  = sm + T_ * S_;

    const int b   = blockIdx.x;
    const int tid = threadIdx.x;
    const int base = b * T_ * U1_;

    // Stage into padded SMEM layout (coalesced gmem reads).
    for (int i = tid; i < T_ * U1_; i += 128) {
        const int t = i / U1_;
        const int u = i - t * U1_;
        blank_s[t * S_ + u] = g_blank[base + i];
        emit_s [t * S_ + u] = g_emit [base + i];
    }
    __syncthreads();
    if (tid >= 32) return;             // warp 0 runs the DP alone

    const int lane  = tid;
    const int alen  = act_lens[b];
    const int llen  = label_lens[b];
    const int dstar = (alen - 1) + llen;
    const int maxoff = T_ * S_ - 1;

    float a0, a1, a2, a3;
    a0 = (lane == 0) ? 0.0f : NEGV;
    a1 = a2 = a3 = NEGV;

    // Per-cell constants (u fixed per register slot).
    int ob[4], oe[4], dlo[4], dhi[4];
    #pragma unroll
    for (int j = 0; j < 4; ++j) {
        const int u = (lane << 2) + j;
        ob[j]  = -u * S_ + u;            // blank offset at d=1: (d-u-1)*S_+u
        oe[j]  = (1 - u) * S_ + u - 1;   // emit  offset at d=1: (d-u)*S_+u-1
        dlo[j] = u;                      // t>=0  <=> d >= u
        dhi[j] = u + T_ - 1;             // t<=T-1<=> d <= u+T-1
    }

    for (int d = 1; d <= dstar; ++d) {
        const float am1 = __shfl_up_sync(0xffffffffu, a3, 1);
        const float ap0 = am1, ap1 = a0, ap2 = a1, ap3 = a2;
        const float ac0 = a0,  ac1 = a1, ac2 = a2, ac3 = a3;
        float ap[4] = { ap0, ap1, ap2, ap3 };
        float ac[4] = { ac0, ac1, ac2, ac3 };
        float na[4];
        #pragma unroll
        for (int j = 0; j < 4; ++j) {
            const int u = (lane << 2) + j;
            const int obc = min(max(ob[j], 0), maxoff);
            const int oec = min(max(oe[j], 0), maxoff);
            const float bl = blank_s[obc];
            const float em = emit_s[oec];
            const bool phi = (d <= dhi[j]);
            const bool pt  = (d >  dlo[j]) && phi;                 // t >= 1
            const bool pl  = (u >= 1) && (d >= dlo[j]) && phi;     // t >= 0, u >= 1
            const float top  = pt ? (ac[j] + bl) : NEGV;
            const float left = pl ? (ap[j] + em) : NEGV;
            const float mx = fmaxf(top, left);
            const float mn = fminf(top, left);
            na[j] = mx + __logf(1.0f + __expf(mn - mx));
            ob[j] += S_;
            oe[j] += S_;
        }
        a0 = na[0]; a1 = na[1]; a2 = na[2]; a3 = na[3];
    }

    // Extract alpha(alen-1, llen): lane llen>>2, slot llen&3.
    const int slot = llen & 3;
    float r = (slot == 0) ? a0 : (slot == 1) ? a1 : (slot == 2) ? a2 : a3;
    r = __shfl_sync(0xffffffffu, r, llen >> 2);
    if (lane == 0)
        g_cost[b] = -(r + blank_s[(alen - 1) * S_ + llen]);
    __threadfence();

    // Last block to finish performs the deterministic fixed-order mean.
    if (lane == 0) {
        const int prev = atomicAdd(&g_done, 1);
        if (prev == B_ - 1) {
            __threadfence();
            float s = 0.0f;
            #pragma unroll
            for (int i = 0; i < B_; ++i) s += g_cost[i];
            out[0] = s / (float)B_;
            g_done = 0;               // reset for next graph replay
        }
    }
}

// ---------------------------------------------------------------------------
extern "C" void kernel_launch(void* const* d_in, const int* in_sizes, int n_in,
                              void* d_out, int out_size)
{
    const float* acts       = (const float*)d_in[0];
    const int*   labels     = (const int*)  d_in[1];
    const int*   act_lens   = (const int*)  d_in[2];
    const int*   label_lens = (const int*)  d_in[3];
    float*       out        = (float*)      d_out;

    const int rows   = B_ * T_ * U1_;          // 323,200 rows
    const int wpb    = 8;                      // warps per block
    const int blocks = (rows + wpb - 1) / wpb; // 40,400

    rnnt_softmax_kernel<<<blocks, wpb * 32>>>(acts, labels, label_lens);

    const size_t smemBytes = (size_t)2 * T_ * S_ * sizeof(float);  // 163,200 B
    cudaFuncSetAttribute(rnnt_dp_kernel,
                         cudaFuncAttributeMaxDynamicSharedMemorySize,
                         (int)smemBytes);
    rnnt_dp_kernel<<<B_, 128, smemBytes>>>(act_lens, label_lens, out);
}

// round 5
// speedup vs baseline: 1.6980x; 1.0786x over previous
#include <cuda_runtime.h>

#define B_   16
#define T_   200
#define U1_  101
#define U_   100
#define V_   512
#define ND_  300          /* time-diagonals: d = t+u in [0, 299] */
#define DW_  104          /* padded diagonal width (u slots), multiple of 4 */
#define PH_  152          /* diagonal rows staged per phase */
#define PAD_ 128          /* SMEM guard pad (floats): lanes 26-31 overread rows */
#define NEGV (-1e30f)

// Diagonal-major scratch: [b][d][u].  emitD is shifted: slot u+1 holds emit(t,u),
// so cell (d,u)'s deps (blank[t-1][u], emit[t][u-1]) BOTH sit at row d-1, slot u.
__device__ float g_blankD[B_ * ND_ * DW_];
__device__ float g_emitD [B_ * ND_ * DW_];
__device__ volatile float g_cost[B_];
__device__ int   g_done = 0;

// ---------------------------------------------------------------------------
// Kernel 0: fill diag-major arrays with NEGV so invalid cells need no
// predicates in the DP inner loop.
// ---------------------------------------------------------------------------
__global__ void __launch_bounds__(256) rnnt_init_kernel()
{
    const int i = blockIdx.x * blockDim.x + threadIdx.x;
    const int n4 = (B_ * ND_ * DW_) / 4;
    if (i < n4) {
        float4 v = make_float4(NEGV, NEGV, NEGV, NEGV);
        reinterpret_cast<float4*>(g_blankD)[i] = v;
        reinterpret_cast<float4*>(g_emitD)[i]  = v;
    }
}

// ---------------------------------------------------------------------------
// Kernel 1: per-row log-softmax stats. One warp per (b,t,u) row of V=512.
// Writes results straight into the diagonal-major layout.
// ---------------------------------------------------------------------------
__global__ void __launch_bounds__(256) rnnt_softmax_kernel(
    const float* __restrict__ acts,
    const int*   __restrict__ labels,
    const int*   __restrict__ label_lens)
{
    const int warp = (blockIdx.x * blockDim.x + threadIdx.x) >> 5;
    const int lane = threadIdx.x & 31;
    const int R = B_ * T_ * U1_;
    if (warp >= R) return;

    const int u = warp % U1_;
    const int t = (warp / U1_) % T_;
    const int b = warp / (T_ * U1_);

    const float4* __restrict__ p =
        reinterpret_cast<const float4*>(acts + (size_t)warp * V_);
    float4 v0 = __ldcs(p + lane);
    float4 v1 = __ldcs(p + lane + 32);
    float4 v2 = __ldcs(p + lane + 64);
    float4 v3 = __ldcs(p + lane + 96);

    // max reduce
    float m = fmaxf(fmaxf(fmaxf(v0.x, v0.y), fmaxf(v0.z, v0.w)),
                    fmaxf(fmaxf(v1.x, v1.y), fmaxf(v1.z, v1.w)));
    m = fmaxf(m, fmaxf(fmaxf(fmaxf(v2.x, v2.y), fmaxf(v2.z, v2.w)),
                       fmaxf(fmaxf(v3.x, v3.y), fmaxf(v3.z, v3.w))));
    #pragma unroll
    for (int off = 16; off > 0; off >>= 1)
        m = fmaxf(m, __shfl_xor_sync(0xffffffffu, m, off));

    // sum(exp(x - m)) reduce
    float s = __expf(v0.x - m) + __expf(v0.y - m) + __expf(v0.z - m) + __expf(v0.w - m)
            + __expf(v1.x - m) + __expf(v1.y - m) + __expf(v1.z - m) + __expf(v1.w - m)
            + __expf(v2.x - m) + __expf(v2.y - m) + __expf(v2.z - m) + __expf(v2.w - m)
            + __expf(v3.x - m) + __expf(v3.y - m) + __expf(v3.z - m) + __expf(v3.w - m);
    #pragma unroll
    for (int off = 16; off > 0; off >>= 1)
        s += __shfl_xor_sync(0xffffffffu, s, off);

    const float lse = m + __logf(s);

    const float blank_logit = __shfl_sync(0xffffffffu, v0.x, 0);

    int lbl = 0;
    if (u < U_) lbl = labels[b * U_ + u];
    const int j   = lbl >> 2;
    const int src = j & 31;
    const int k   = j >> 5;
    const int c   = lbl & 3;
    float4 sel = (k == 0) ? v0 : (k == 1) ? v1 : (k == 2) ? v2 : v3;
    float cand = (c == 0) ? sel.x : (c == 1) ? sel.y : (c == 2) ? sel.z : sel.w;
    const float label_logit = __shfl_sync(0xffffffffu, cand, src);

    if (lane == 0) {
        const int llen = label_lens[b];
        const int d    = t + u;
        const int base = b * ND_ * DW_ + d * DW_;
        g_blankD[base + u] = blank_logit - lse;
        if (u < llen)
            g_emitD[base + u + 1] = label_logit - lse;
        // else: stays NEGV from init
    }
}

// ---------------------------------------------------------------------------
// Kernel 2: forward DP — warp-synchronous wavefront over diag-major SMEM.
// Lane L holds alpha for u = 4L..4L+3 in registers (lanes 26-31 are dead
// weight: u >= 104 garbage stays finite and never flows down to valid u).
// Per diagonal: 1 shfl + 2 LDS.128 + branch-free logaddexp x4.
// Two staging phases (SMEM holds 152 diagonal rows at a time) + guard pad.
// ---------------------------------------------------------------------------
__global__ void __launch_bounds__(128) rnnt_dp_kernel(
    const int* __restrict__ act_lens,
    const int* __restrict__ label_lens,
    float* __restrict__ out)
{
    extern __shared__ float sm[];
    float* Bs = sm;                 // PH_ * DW_
    float* Es = sm + PH_ * DW_;     // PH_ * DW_  (+ PAD_ guard after)

    const int b    = blockIdx.x;
    const int tid  = threadIdx.x;
    const int lane = tid & 31;

    const float4* gB = reinterpret_cast<const float4*>(g_blankD + b * ND_ * DW_);
    const float4* gE = reinterpret_cast<const float4*>(g_emitD  + b * ND_ * DW_);
    float4* sB = reinterpret_cast<float4*>(Bs);
    float4* sE = reinterpret_cast<float4*>(Es);

    // Stage phase 0: diagonal rows [0, PH_).
    {
        const int n4 = PH_ * DW_ / 4;      // 3952
        for (int i = tid; i < n4; i += 128) { sB[i] = gB[i]; sE[i] = gE[i]; }
    }
    __syncthreads();

    const int alen  = act_lens[b];
    const int llen  = label_lens[b];
    const int dstar = (alen - 1) + llen;   // in [199, 299]

    float a0 = 0.f, a1 = NEGV, a2 = NEGV, a3 = NEGV;
    const int ubase = lane << 2;

    if (tid < 32) {
        a0 = (lane == 0) ? 0.0f : NEGV;
        const int dend = (dstar < PH_) ? dstar : PH_;
        int off = ubase;                   // row(d-1)=d-1, slot ubase
        for (int d = 1; d <= dend; ++d) {
            const float am1 = __shfl_up_sync(0xffffffffu, a3, 1);
            const float4 bl = *reinterpret_cast<const float4*>(Bs + off);
            const float4 em = *reinterpret_cast<const float4*>(Es + off);
            float ac[4] = { a0, a1, a2, a3 };
            float ap[4] = { am1, a0, a1, a2 };
            const float blv[4] = { bl.x, bl.y, bl.z, bl.w };
            const float emv[4] = { em.x, em.y, em.z, em.w };
            float na[4];
            #pragma unroll
            for (int j = 0; j < 4; ++j) {
                const float top  = ac[j] + blv[j];
                const float left = ap[j] + emv[j];
                const float mx = fmaxf(top, left);
                const float mn = fminf(top, left);
                na[j] = mx + __logf(1.0f + __expf(mn - mx));
            }
            a0 = na[0]; a1 = na[1]; a2 = na[2]; a3 = na[3];
            off += DW_;
        }
    }
    __syncthreads();

    // Stage phase 1: diagonal rows [PH_, 299)  (147 rows).
    {
        const int base4 = PH_ * DW_ / 4;
        const int m4    = (ND_ - 1 - PH_) * DW_ / 4;   // 147*26 = 3822
        for (int i = tid; i < m4; i += 128) { sB[i] = gB[base4 + i]; sE[i] = gE[base4 + i]; }
    }
    __syncthreads();

    if (tid < 32) {
        int off = ubase;                   // row(d-1)-PH_ = 0 at d = PH_+1
        for (int d = PH_ + 1; d <= dstar; ++d) {
            const float am1 = __shfl_up_sync(0xffffffffu, a3, 1);
            const float4 bl = *reinterpret_cast<const float4*>(Bs + off);
            const float4 em = *reinterpret_cast<const float4*>(Es + off);
            float ac[4] = { a0, a1, a2, a3 };
            float ap[4] = { am1, a0, a1, a2 };
            const float blv[4] = { bl.x, bl.y, bl.z, bl.w };
            const float emv[4] = { em.x, em.y, em.z, em.w };
            float na[4];
            #pragma unroll
            for (int j = 0; j < 4; ++j) {
                const float top  = ac[j] + blv[j];
                const float left = ap[j] + emv[j];
                const float mx = fmaxf(top, left);
                const float mn = fminf(top, left);
                na[j] = mx + __logf(1.0f + __expf(mn - mx));
            }
            a0 = na[0]; a1 = na[1]; a2 = na[2]; a3 = na[3];
            off += DW_;
        }

        // Extract alpha(alen-1, llen) and final blank from gmem row dstar.
        const int slot = llen & 3;
        float r = (slot == 0) ? a0 : (slot == 1) ? a1 : (slot == 2) ? a2 : a3;
        r = __shfl_sync(0xffffffffu, r, llen >> 2);
        if (lane == 0) {
            const float fb = g_blankD[b * ND_ * DW_ + dstar * DW_ + llen];
            g_cost[b] = -(r + fb);
            __threadfence();
            const int prev = atomicAdd(&g_done, 1);
            if (prev == B_ - 1) {
                __threadfence();
                float s = 0.0f;
                #pragma unroll
                for (int i = 0; i < B_; ++i) s += g_cost[i];
                out[0] = s / (float)B_;
                g_done = 0;            // reset for next graph replay
            }
        }
    }
}

// ---------------------------------------------------------------------------
extern "C" void kernel_launch(void* const* d_in, const int* in_sizes, int n_in,
                              void* d_out, int out_size)
{
    const float* acts       = (const float*)d_in[0];
    const int*   labels     = (const int*)  d_in[1];
    const int*   act_lens   = (const int*)  d_in[2];
    const int*   label_lens = (const int*)  d_in[3];
    float*       out        = (float*)      d_out;

    // Kernel 0: NEGV-fill diag-major scratch (3.8 MB).
    {
        const int n4 = (B_ * ND_ * DW_) / 4;
        rnnt_init_kernel<<<(n4 + 255) / 256, 256>>>();
    }

    // Kernel 1: log-softmax stats.
    const int rows   = B_ * T_ * U1_;
    const int wpb    = 8;
    const int blocks = (rows + wpb - 1) / wpb;
    rnnt_softmax_kernel<<<blocks, wpb * 32>>>(acts, labels, label_lens);

    // Kernel 2: DP + finalize.
    const size_t smemBytes =
        (size_t)(2 * PH_ * DW_ + PAD_) * sizeof(float);   // 126,976 B
    cudaFuncSetAttribute(rnnt_dp_kernel,
                         cudaFuncAttributeMaxDynamicSharedMemorySize,
                         (int)smemBytes);
    rnnt_dp_kernel<<<B_, 128, smemBytes>>>(act_lens, label_lens, out);
}